// round 14
// baseline (speedup 1.0000x reference)
#include <cuda_runtime.h>

#define NN 200000
#define NE 2000000
#define NG 10000
#define SCAN_BLK 196          // ceil(NN/1024)
#define EMB_BLK 782           // ceil(NN/256)

typedef unsigned long long ull;

// -------- scratch (static device globals; zero-initialized by CUDA) --------
__device__ float d_h[NN * 32];
__device__ float d_z[NN * 32];
__device__ float d_z2[NN * 32];
__device__ float d_pool[NG * 32];
__device__ float d_cnt[NG];
__device__ float d_bnstat[2 * 64];
// CSR
__device__ int d_deg[NN];
__device__ int d_rowptr[NN + 1];
__device__ int d_cursor[NN];
__device__ float4 d_csr[NE];          // (src bits, a0, a1, a2)
// decoupled-lookback scan state
__device__ int d_partial[SCAN_BLK];
__device__ int d_prefix[SCAN_BLK];
__device__ int d_flag[SCAN_BLK];

// -------- packed f32x2 helpers --------
__device__ __forceinline__ ull fma2(ull a, ull b, ull c) {
    ull d;
    asm("fma.rn.f32x2 %0, %1, %2, %3;" : "=l"(d) : "l"(a), "l"(b), "l"(c));
    return d;
}
__device__ __forceinline__ float lo32(ull a) { return __uint_as_float((unsigned)a); }
__device__ __forceinline__ float hi32(ull a) { return __uint_as_float((unsigned)(a >> 32)); }
__device__ __forceinline__ ull pack2(float x, float y) {
    ull r;
    asm("mov.b64 %0, {%1, %2};" : "=l"(r) : "f"(x), "f"(y));
    return r;
}

// -------- CSR build --------
__global__ void k_hist(const int* __restrict__ ei) {
    int e = blockIdx.x * blockDim.x + threadIdx.x;
    if (e < NE) atomicAdd(&d_deg[ei[NE + e]], 1);
}

// single-pass scan over deg -> rowptr/cursor, decoupled lookback.
__global__ void __launch_bounds__(1024) k_scan() {
    int b = blockIdx.x;
    int i = b * 1024 + threadIdx.x;
    int deg = (i < NN) ? d_deg[i] : 0;
    int v = deg;
    int lane = threadIdx.x & 31, w = threadIdx.x >> 5;
#pragma unroll
    for (int off = 1; off < 32; off <<= 1) {
        int t = __shfl_up_sync(0xffffffffu, v, off);
        if (lane >= off) v += t;
    }
    __shared__ int wsum[32];
    __shared__ int s_base;
    if (lane == 31) wsum[w] = v;
    __syncthreads();
    if (w == 0) {
        int s = wsum[lane];
#pragma unroll
        for (int off = 1; off < 32; off <<= 1) {
            int t = __shfl_up_sync(0xffffffffu, s, off);
            if (lane >= off) s += t;
        }
        wsum[lane] = s;
        int total = __shfl_sync(0xffffffffu, s, 31);
        if (b == 0) {
            if (lane == 0) {
                d_prefix[0] = total;
                __threadfence();
                atomicExch(&d_flag[0], 2);
                s_base = 0;
            }
        } else {
            if (lane == 0) {
                d_partial[b] = total;
                __threadfence();
                atomicExch(&d_flag[b], 1);
            }
            int sum = 0;
            int wstart = b - 1;
            bool done = false;
            while (!done) {
                int j = wstart - lane;
                int f = 2, val = 0;
                if (j >= 0) {
                    do { f = atomicAdd(&d_flag[j], 0); } while (f == 0);
                    val = (f == 2) ? atomicAdd(&d_prefix[j], 0)
                                   : atomicAdd(&d_partial[j], 0);
                }
                unsigned ball = __ballot_sync(0xffffffffu, f == 2);
                int contrib;
                if (ball) {
                    int firstdone = __ffs(ball) - 1;
                    contrib = (lane <= firstdone) ? val : 0;
                    done = true;
                } else {
                    contrib = val;
                    wstart -= 32;
                }
                sum += __reduce_add_sync(0xffffffffu, contrib);
            }
            if (lane == 0) {
                d_prefix[b] = sum + total;
                __threadfence();
                atomicExch(&d_flag[b], 2);
                s_base = sum;
            }
        }
    }
    __syncthreads();
    if (w > 0) v += wsum[w - 1];
    if (i < NN) {
        int incl = s_base + v;
        d_rowptr[i + 1] = incl;
        d_cursor[i] = incl - deg;
    }
    if (b == 0 && threadIdx.x == 0) d_rowptr[0] = 0;
}

// -------- fused CSR scatter + node embedding (reg-capped) --------
__global__ void __launch_bounds__(256, 6) k_scatter(const int* __restrict__ ei,
                                                    const float* __restrict__ ea,
                                                    const float* __restrict__ x,
                                                    const float* __restrict__ nw,
                                                    const float* __restrict__ nb) {
    __shared__ float xs[256 * 14];
    __shared__ float w[14 * 32];
    __shared__ float b[32];
    int tid = threadIdx.x;
    int e = blockIdx.x * 256 + tid;
    int s = 0, d = 0;
    float a0 = 0.f, a1 = 0.f, a2 = 0.f;
    bool ve = e < NE;
    if (ve) {
        s = ei[e];
        d = ei[NE + e];
        a0 = ea[3 * e];
        a1 = ea[3 * e + 1];
        a2 = ea[3 * e + 2];
    }
    bool emb = blockIdx.x < EMB_BLK;
    int base = blockIdx.x * 256;
    int rows = 0;
    if (emb) {
        rows = min(256, NN - base);
        for (int i = tid; i < 448; i += 256) w[i] = nw[i];
        if (tid < 32) b[tid] = nb[tid];
        for (int i = tid; i < rows * 14; i += 256) xs[i] = x[base * 14 + i];
    }
    __syncthreads();
    if (ve) {
        float4 p;
        p.x = __int_as_float(s);
        p.y = a0; p.z = a1; p.w = a2;
        int pos = atomicAdd(&d_cursor[d], 1);
        d_csr[pos] = p;
    }
    if (emb && tid < rows) {
        float xv[14];
#pragma unroll
        for (int k = 0; k < 14; k++) xv[k] = xs[tid * 14 + k];
#pragma unroll
        for (int f = 0; f < 32; f++) {
            float o = b[f];
#pragma unroll
            for (int k = 0; k < 14; k++) o += xv[k] * w[k * 32 + f];
            d_h[(base + tid) * 32 + f] = o;
        }
    }
}

// -------- CSR aggregation: z[n] = h[n] + sum_in relu(h[src] + attr@ew + eb) --------
// 8 lanes per node, 32 nodes per 256-thread block, unroll x4 for MLP.
__global__ void __launch_bounds__(256) k_agg(const float* __restrict__ ew,
                                             const float* __restrict__ eb) {
    __shared__ float w[96];
    __shared__ float b[32];
    for (int i = threadIdx.x; i < 96; i += 256) w[i] = ew[i];
    if (threadIdx.x < 32) b[threadIdx.x] = eb[threadIdx.x];
    __syncthreads();
    int tid = threadIdx.x;
    int node = blockIdx.x * 32 + (tid >> 3);
    int q = tid & 7;
    int f0 = q * 4;
    int start = __ldg(d_rowptr + node);
    int end = __ldg(d_rowptr + node + 1);
    float w0a = w[f0], w0b = w[f0 + 1], w0c = w[f0 + 2], w0d = w[f0 + 3];
    float w1a = w[32 + f0], w1b = w[32 + f0 + 1], w1c = w[32 + f0 + 2], w1d = w[32 + f0 + 3];
    float w2a = w[64 + f0], w2b = w[64 + f0 + 1], w2c = w[64 + f0 + 2], w2d = w[64 + f0 + 3];
    float ba = b[f0], bb = b[f0 + 1], bc = b[f0 + 2], bd = b[f0 + 3];
    float ax = 0.f, ay = 0.f, az = 0.f, aw = 0.f;
    int i = start;
    for (; i + 4 <= end; i += 4) {
        float4 p0 = __ldg(d_csr + i);
        float4 p1 = __ldg(d_csr + i + 1);
        float4 p2 = __ldg(d_csr + i + 2);
        float4 p3 = __ldg(d_csr + i + 3);
        float4 h0 = __ldg((const float4*)(d_h + __float_as_int(p0.x) * 32 + f0));
        float4 h1 = __ldg((const float4*)(d_h + __float_as_int(p1.x) * 32 + f0));
        float4 h2 = __ldg((const float4*)(d_h + __float_as_int(p2.x) * 32 + f0));
        float4 h3 = __ldg((const float4*)(d_h + __float_as_int(p3.x) * 32 + f0));
        ax += fmaxf(0.f, h0.x + ba + p0.y * w0a + p0.z * w1a + p0.w * w2a);
        ay += fmaxf(0.f, h0.y + bb + p0.y * w0b + p0.z * w1b + p0.w * w2b);
        az += fmaxf(0.f, h0.z + bc + p0.y * w0c + p0.z * w1c + p0.w * w2c);
        aw += fmaxf(0.f, h0.w + bd + p0.y * w0d + p0.z * w1d + p0.w * w2d);
        ax += fmaxf(0.f, h1.x + ba + p1.y * w0a + p1.z * w1a + p1.w * w2a);
        ay += fmaxf(0.f, h1.y + bb + p1.y * w0b + p1.z * w1b + p1.w * w2b);
        az += fmaxf(0.f, h1.z + bc + p1.y * w0c + p1.z * w1c + p1.w * w2c);
        aw += fmaxf(0.f, h1.w + bd + p1.y * w0d + p1.z * w1d + p1.w * w2d);
        ax += fmaxf(0.f, h2.x + ba + p2.y * w0a + p2.z * w1a + p2.w * w2a);
        ay += fmaxf(0.f, h2.y + bb + p2.y * w0b + p2.z * w1b + p2.w * w2b);
        az += fmaxf(0.f, h2.z + bc + p2.y * w0c + p2.z * w1c + p2.w * w2c);
        aw += fmaxf(0.f, h2.w + bd + p2.y * w0d + p2.z * w1d + p2.w * w2d);
        ax += fmaxf(0.f, h3.x + ba + p3.y * w0a + p3.z * w1a + p3.w * w2a);
        ay += fmaxf(0.f, h3.y + bb + p3.y * w0b + p3.z * w1b + p3.w * w2b);
        az += fmaxf(0.f, h3.z + bc + p3.y * w0c + p3.z * w1c + p3.w * w2c);
        aw += fmaxf(0.f, h3.w + bd + p3.y * w0d + p3.z * w1d + p3.w * w2d);
    }
    for (; i < end; i++) {
        float4 p0 = __ldg(d_csr + i);
        float4 h0 = __ldg((const float4*)(d_h + __float_as_int(p0.x) * 32 + f0));
        ax += fmaxf(0.f, h0.x + ba + p0.y * w0a + p0.z * w1a + p0.w * w2a);
        ay += fmaxf(0.f, h0.y + bb + p0.y * w0b + p0.z * w1b + p0.w * w2b);
        az += fmaxf(0.f, h0.z + bc + p0.y * w0c + p0.z * w1c + p0.w * w2c);
        aw += fmaxf(0.f, h0.w + bd + p0.y * w0d + p0.z * w1d + p0.w * w2d);
    }
    float4 hs = *(const float4*)(d_h + node * 32 + f0);
    float4 o;
    o.x = hs.x + ax; o.y = hs.y + ay; o.z = hs.z + az; o.w = hs.w + aw;
    *(float4*)(d_z + node * 32 + f0) = o;
}

// -------- MLP: 128 nodes/block, smem-staged, fma2 register-blocked --------
#define ZS_OFF 0
#define HS_OFF 4224
#define W1_OFF (HS_OFF + 128 * 81)
#define W2_OFF (W1_OFF + 32 * 80)
#define B1_OFF (W2_OFF + 2400)
#define MLP_SMEM ((B1_OFF + 80) * 4)

__global__ void __launch_bounds__(256) k_mlp(int l,
        const float* __restrict__ w1, const float* __restrict__ b1,
        const float* __restrict__ w2, const float* __restrict__ b2) {
    extern __shared__ float sm[];
    float* Zs = sm + ZS_OFF;
    float* Hs = sm + HS_OFF;
    float* W1s = sm + W1_OFF;
    float* W2s = sm + W2_OFF;
    float* B1s = sm + B1_OFF;
    int tid = threadIdx.x;
    const float* w1l = w1 + l * 2400;
    const float* w2l = w2 + l * 2400;
    for (int i = tid; i < 32 * 80; i += 256) {
        int k = i / 80, j = i % 80;
        W1s[i] = (j < 75) ? w1l[k * 75 + j] : 0.f;
    }
    for (int i = tid; i < 2400; i += 256) W2s[i] = w2l[i];
    if (tid < 80) B1s[tid] = (tid < 75) ? b1[l * 75 + tid] : 0.f;

    int base = blockIdx.x * 128;
    int rows = min(128, NN - base);
    for (int i = tid; i < rows * 32; i += 256)
        Zs[(i >> 5) * 33 + (i & 31)] = d_z[base * 32 + i];
    __syncthreads();

    int lane = tid & 31;
    int wid = tid >> 5;

    // ---- phase 1 ----
    {
        int jb2 = wid * 5;
        const ull* B1u = (const ull*)B1s;
        ull acc[4][5];
#pragma unroll
        for (int jj = 0; jj < 5; jj++) {
            ull bias = B1u[jb2 + jj];
            acc[0][jj] = bias; acc[1][jj] = bias; acc[2][jj] = bias; acc[3][jj] = bias;
        }
#pragma unroll 4
        for (int k = 0; k < 32; k++) {
            const ull* wr = (const ull*)(W1s + k * 80) + jb2;
            ull w0 = wr[0], w1v = wr[1], w2v = wr[2], w3 = wr[3], w4 = wr[4];
#pragma unroll
            for (int i = 0; i < 4; i++) {
                int n = lane + 32 * i;
                float zv = (n < rows) ? Zs[n * 33 + k] : 0.f;
                ull zp = pack2(zv, zv);
                acc[i][0] = fma2(zp, w0, acc[i][0]);
                acc[i][1] = fma2(zp, w1v, acc[i][1]);
                acc[i][2] = fma2(zp, w2v, acc[i][2]);
                acc[i][3] = fma2(zp, w3, acc[i][3]);
                acc[i][4] = fma2(zp, w4, acc[i][4]);
            }
        }
        int jb = wid * 10;
#pragma unroll
        for (int i = 0; i < 4; i++) {
            int n = lane + 32 * i;
#pragma unroll
            for (int jj = 0; jj < 5; jj++) {
                Hs[n * 81 + jb + 2 * jj]     = fmaxf(0.f, lo32(acc[i][jj]));
                Hs[n * 81 + jb + 2 * jj + 1] = fmaxf(0.f, hi32(acc[i][jj]));
            }
        }
    }
    __syncthreads();

    // ---- phase 2 ----
    int f0 = wid * 4;
    ull bias0 = pack2(__ldg(b2 + l * 32 + f0), __ldg(b2 + l * 32 + f0 + 1));
    ull bias1 = pack2(__ldg(b2 + l * 32 + f0 + 2), __ldg(b2 + l * 32 + f0 + 3));
    ull acc2[4][2];
#pragma unroll
    for (int i = 0; i < 4; i++) { acc2[i][0] = bias0; acc2[i][1] = bias1; }
#pragma unroll 5
    for (int k = 0; k < 75; k++) {
        ulonglong2 wv = *(const ulonglong2*)(W2s + k * 32 + f0);
#pragma unroll
        for (int i = 0; i < 4; i++) {
            float hv = Hs[(lane + 32 * i) * 81 + k];
            ull hp = pack2(hv, hv);
            acc2[i][0] = fma2(hp, wv.x, acc2[i][0]);
            acc2[i][1] = fma2(hp, wv.y, acc2[i][1]);
        }
    }
    float s[4] = {0.f, 0.f, 0.f, 0.f};
    float q[4] = {0.f, 0.f, 0.f, 0.f};
#pragma unroll
    for (int i = 0; i < 4; i++) {
        int n = lane + 32 * i;
        if (n < rows) {
            float v0 = lo32(acc2[i][0]), v1 = hi32(acc2[i][0]);
            float v2 = lo32(acc2[i][1]), v3 = hi32(acc2[i][1]);
            s[0] += v0; q[0] += v0 * v0;
            s[1] += v1; q[1] += v1 * v1;
            s[2] += v2; q[2] += v2 * v2;
            s[3] += v3; q[3] += v3 * v3;
        }
    }
    __syncthreads();
#pragma unroll
    for (int i = 0; i < 4; i++) {
        int n = lane + 32 * i;
        Zs[n * 33 + f0]     = lo32(acc2[i][0]);
        Zs[n * 33 + f0 + 1] = hi32(acc2[i][0]);
        Zs[n * 33 + f0 + 2] = lo32(acc2[i][1]);
        Zs[n * 33 + f0 + 3] = hi32(acc2[i][1]);
    }
#pragma unroll
    for (int off = 16; off; off >>= 1) {
#pragma unroll
        for (int c = 0; c < 4; c++) {
            s[c] += __shfl_down_sync(0xffffffffu, s[c], off);
            q[c] += __shfl_down_sync(0xffffffffu, q[c], off);
        }
    }
    if (lane == 0) {
#pragma unroll
        for (int c = 0; c < 4; c++) {
            atomicAdd(&d_bnstat[l * 64 + f0 + c], s[c]);
            atomicAdd(&d_bnstat[l * 64 + 32 + f0 + c], q[c]);
        }
    }
    __syncthreads();
    for (int i = tid; i < rows * 32; i += 256)
        d_z2[base * 32 + i] = Zs[(i >> 5) * 33 + (i & 31)];
}

// -------- BN normalize + relu (scale computed in-block); mode 0: write h; mode 1: pool --------
__global__ void k_bnnorm(int l, int mode, const int* __restrict__ batch,
                         const float* __restrict__ bng, const float* __restrict__ bnb) {
    __shared__ float sc[32], sh[32];
    if (threadIdx.x < 32) {
        int f = threadIdx.x;
        float s = d_bnstat[l * 64 + f];
        float q = d_bnstat[l * 64 + 32 + f];
        float mu = s / (float)NN;
        float var = q / (float)NN - mu * mu;
        float r = rsqrtf(var + 1e-5f);
        float scv = bng[l * 32 + f] * r;
        sc[f] = scv;
        sh[f] = bnb[l * 32 + f] - mu * scv;
    }
    __syncthreads();
    int i = blockIdx.x * blockDim.x + threadIdx.x;
    if (i >= NN * 8) return;
    float4 v = ((const float4*)d_z2)[i];
    int f0 = (i & 7) * 4;
    float4 r;
    r.x = fmaxf(0.f, v.x * sc[f0 + 0] + sh[f0 + 0]);
    r.y = fmaxf(0.f, v.y * sc[f0 + 1] + sh[f0 + 1]);
    r.z = fmaxf(0.f, v.z * sc[f0 + 2] + sh[f0 + 2]);
    r.w = fmaxf(0.f, v.w * sc[f0 + 3] + sh[f0 + 3]);
    if (mode == 0) {
        ((float4*)d_h)[i] = r;
    } else {
        int n = i >> 3;
        int g = __ldg(batch + n);
        float* p = d_pool + g * 32 + f0;
        asm volatile("red.global.add.v4.f32 [%0], {%1,%2,%3,%4};"
                     :: "l"(p), "f"(r.x), "f"(r.y), "f"(r.z), "f"(r.w) : "memory");
        if ((i & 7) == 0) atomicAdd(&d_cnt[g], 1.f);
    }
}

// -------- readout head --------
__global__ void k_head(const float* __restrict__ w1, const float* __restrict__ b1,
                       const float* __restrict__ w2, const float* __restrict__ b2,
                       float* __restrict__ out) {
    __shared__ float W1[32 * 16];
    __shared__ float B1[16];
    __shared__ float W2[32];
    __shared__ float B2[2];
    for (int i = threadIdx.x; i < 512; i += blockDim.x) W1[i] = w1[i];
    if (threadIdx.x < 16) B1[threadIdx.x] = b1[threadIdx.x];
    if (threadIdx.x < 32) W2[threadIdx.x] = w2[threadIdx.x];
    if (threadIdx.x < 2) B2[threadIdx.x] = b2[threadIdx.x];
    __syncthreads();
    int g = blockIdx.x * blockDim.x + threadIdx.x;
    if (g >= NG) return;
    float inv = 1.f / fmaxf(d_cnt[g], 1.f);
    float gv[32];
#pragma unroll
    for (int k = 0; k < 32; k++) gv[k] = d_pool[g * 32 + k] * inv;
    float o0 = B2[0], o1 = B2[1];
#pragma unroll
    for (int j = 0; j < 16; j++) {
        float hj = B1[j];
#pragma unroll
        for (int k = 0; k < 32; k++) hj += gv[k] * W1[k * 16 + j];
        hj = fmaxf(hj, 0.f);
        o0 += hj * W2[j * 2 + 0];
        o1 += hj * W2[j * 2 + 1];
    }
    out[g * 2 + 0] = o0;
    out[g * 2 + 1] = o1;
}

// -------- tail: zero all accumulators for the NEXT run --------
// Statics are zero-initialized, so the first run sees zeros; every run
// re-establishes the invariant at its end (graph-replay safe, deterministic).
__global__ void k_tail() {
    int i = blockIdx.x * blockDim.x + threadIdx.x;
    const int n0 = NG * 32, n1 = n0 + NG, n2 = n1 + 128, n3 = n2 + NN, n4 = n3 + SCAN_BLK;
    for (; i < n4; i += gridDim.x * blockDim.x) {
        if (i < n0) d_pool[i] = 0.f;
        else if (i < n1) d_cnt[i - n0] = 0.f;
        else if (i < n2) d_bnstat[i - n1] = 0.f;
        else if (i < n3) d_deg[i - n2] = 0;
        else d_flag[i - n3] = 0;
    }
}

extern "C" void kernel_launch(void* const* d_in, const int* in_sizes, int n_in,
                              void* d_out, int out_size) {
    const float* x    = (const float*)d_in[0];
    const int*   ei   = (const int*)  d_in[1];
    const float* ea   = (const float*)d_in[2];
    const int*   batch= (const int*)  d_in[3];
    const float* nw   = (const float*)d_in[4];
    const float* nb   = (const float*)d_in[5];
    const float* ew   = (const float*)d_in[6];
    const float* eb   = (const float*)d_in[7];
    const float* w1   = (const float*)d_in[8];
    const float* b1   = (const float*)d_in[9];
    const float* w2   = (const float*)d_in[10];
    const float* b2   = (const float*)d_in[11];
    const float* bng  = (const float*)d_in[12];
    const float* bnb  = (const float*)d_in[13];
    const float* l1w  = (const float*)d_in[14];
    const float* l1b  = (const float*)d_in[15];
    const float* l2w  = (const float*)d_in[16];
    const float* l2b  = (const float*)d_in[17];
    float* out = (float*)d_out;

    cudaFuncSetAttribute(k_mlp, cudaFuncAttributeMaxDynamicSharedMemorySize, MLP_SMEM);

    k_hist<<<(NE + 255) / 256, 256>>>(ei);
    k_scan<<<SCAN_BLK, 1024>>>();
    k_scatter<<<(NE + 255) / 256, 256>>>(ei, ea, x, nw, nb);  // fused scatter + embed
    for (int l = 0; l < 2; l++) {
        k_agg<<<NN / 32, 256>>>(ew, eb);
        k_mlp<<<(NN + 127) / 128, 256, MLP_SMEM>>>(l, w1, b1, w2, b2);
        k_bnnorm<<<(NN * 8 + 255) / 256, 256>>>(l, l == 0 ? 0 : 1, batch, bng, bnb);
    }
    k_head<<<(NG + 255) / 256, 256>>>(l1w, l1b, l2w, l2b, out);
    k_tail<<<256, 256>>>();
}

// round 15
// speedup vs baseline: 1.1345x; 1.1345x over previous
#include <cuda_runtime.h>

#define NN 200000
#define NE 2000000
#define NG 10000
#define SCAN_BLK 196          // ceil(NN/1024)

typedef unsigned long long ull;

// -------- scratch (static device globals; no allocation) --------
__device__ float d_h[NN * 32];
__device__ float d_z[NN * 32];
__device__ float d_z2[NN * 32];
__device__ float d_pool[NG * 32];
__device__ float d_cnt[NG];
__device__ float d_bnstat[2 * 64];
// CSR
__device__ int d_deg[NN];
__device__ int d_rowptr[NN + 1];
__device__ int d_cursor[NN];
__device__ float4 d_csr[NE];          // (src*32 bits, a0, a1, a2)
// decoupled-lookback scan state
__device__ int d_partial[SCAN_BLK];
__device__ int d_prefix[SCAN_BLK];
__device__ int d_flag[SCAN_BLK];

// -------- packed f32x2 helpers --------
__device__ __forceinline__ ull fma2(ull a, ull b, ull c) {
    ull d;
    asm("fma.rn.f32x2 %0, %1, %2, %3;" : "=l"(d) : "l"(a), "l"(b), "l"(c));
    return d;
}
__device__ __forceinline__ float lo32(ull a) { return __uint_as_float((unsigned)a); }
__device__ __forceinline__ float hi32(ull a) { return __uint_as_float((unsigned)(a >> 32)); }
__device__ __forceinline__ ull pack2(float x, float y) {
    ull r;
    asm("mov.b64 %0, {%1, %2};" : "=l"(r) : "f"(x), "f"(y));
    return r;
}

// -------- zero accumulators + degree + scan flags --------
__global__ void k_zero() {
    int i = blockIdx.x * blockDim.x + threadIdx.x;
    const int n0 = NG * 32, n1 = n0 + NG, n2 = n1 + 128, n3 = n2 + NN, n4 = n3 + SCAN_BLK;
    for (; i < n4; i += gridDim.x * blockDim.x) {
        if (i < n0) d_pool[i] = 0.f;
        else if (i < n1) d_cnt[i - n0] = 0.f;
        else if (i < n2) d_bnstat[i - n1] = 0.f;
        else if (i < n3) d_deg[i - n2] = 0;
        else d_flag[i - n3] = 0;
    }
}

// -------- CSR build --------
__global__ void k_hist(const int* __restrict__ ei) {
    int e = blockIdx.x * blockDim.x + threadIdx.x;
    if (e < NE) atomicAdd(&d_deg[ei[NE + e]], 1);
}

// single-pass scan over deg -> rowptr/cursor, decoupled lookback.
__global__ void __launch_bounds__(1024) k_scan() {
    int b = blockIdx.x;
    int i = b * 1024 + threadIdx.x;
    int deg = (i < NN) ? d_deg[i] : 0;
    int v = deg;
    int lane = threadIdx.x & 31, w = threadIdx.x >> 5;
#pragma unroll
    for (int off = 1; off < 32; off <<= 1) {
        int t = __shfl_up_sync(0xffffffffu, v, off);
        if (lane >= off) v += t;
    }
    __shared__ int wsum[32];
    __shared__ int s_base;
    if (lane == 31) wsum[w] = v;
    __syncthreads();
    if (w == 0) {
        int s = wsum[lane];
#pragma unroll
        for (int off = 1; off < 32; off <<= 1) {
            int t = __shfl_up_sync(0xffffffffu, s, off);
            if (lane >= off) s += t;
        }
        wsum[lane] = s;
        int total = __shfl_sync(0xffffffffu, s, 31);
        if (b == 0) {
            if (lane == 0) {
                d_prefix[0] = total;
                __threadfence();
                atomicExch(&d_flag[0], 2);
                s_base = 0;
            }
        } else {
            if (lane == 0) {
                d_partial[b] = total;
                __threadfence();
                atomicExch(&d_flag[b], 1);
            }
            int sum = 0;
            int wstart = b - 1;
            bool done = false;
            while (!done) {
                int j = wstart - lane;
                int f = 2, val = 0;
                if (j >= 0) {
                    do { f = atomicAdd(&d_flag[j], 0); } while (f == 0);
                    val = (f == 2) ? atomicAdd(&d_prefix[j], 0)
                                   : atomicAdd(&d_partial[j], 0);
                }
                unsigned ball = __ballot_sync(0xffffffffu, f == 2);
                int contrib;
                if (ball) {
                    int firstdone = __ffs(ball) - 1;
                    contrib = (lane <= firstdone) ? val : 0;
                    done = true;
                } else {
                    contrib = val;
                    wstart -= 32;
                }
                sum += __reduce_add_sync(0xffffffffu, contrib);
            }
            if (lane == 0) {
                d_prefix[b] = sum + total;
                __threadfence();
                atomicExch(&d_flag[b], 2);
                s_base = sum;
            }
        }
    }
    __syncthreads();
    if (w > 0) v += wsum[w - 1];
    if (i < NN) {
        int incl = s_base + v;
        d_rowptr[i + 1] = incl;
        d_cursor[i] = incl - deg;
    }
    if (b == 0 && threadIdx.x == 0) d_rowptr[0] = 0;
}

__global__ void k_scatter(const int* __restrict__ ei, const float* __restrict__ ea) {
    int e = blockIdx.x * blockDim.x + threadIdx.x;
    if (e >= NE) return;
    int s = ei[e];
    int d = ei[NE + e];
    float4 p;
    p.x = __int_as_float(s * 32);     // pre-scaled: row offset into d_h
    p.y = ea[3 * e];
    p.z = ea[3 * e + 1];
    p.w = ea[3 * e + 2];
    int pos = atomicAdd(&d_cursor[d], 1);
    d_csr[pos] = p;
}

// -------- node embedding: h = x @ node_w + node_b --------
__global__ void __launch_bounds__(256) k_embed(const float* __restrict__ x,
                        const float* __restrict__ nw,
                        const float* __restrict__ nb) {
    __shared__ float xs[256 * 14];
    __shared__ float w[14 * 32];
    __shared__ float b[32];
    for (int i = threadIdx.x; i < 448; i += 256) w[i] = nw[i];
    if (threadIdx.x < 32) b[threadIdx.x] = nb[threadIdx.x];
    int base = blockIdx.x * 256;
    int rows = min(256, NN - base);
    for (int i = threadIdx.x; i < rows * 14; i += 256) xs[i] = x[base * 14 + i];
    __syncthreads();
    int tid = threadIdx.x;
    if (tid >= rows) return;
    float xv[14];
#pragma unroll
    for (int k = 0; k < 14; k++) xv[k] = xs[tid * 14 + k];
#pragma unroll
    for (int f = 0; f < 32; f++) {
        float o = b[f];
#pragma unroll
        for (int k = 0; k < 14; k++) o += xv[k] * w[k * 32 + f];
        d_h[(base + tid) * 32 + f] = o;
    }
}

// -------- CSR aggregation: z[n] = h[n] + sum_in relu(h[src] + attr@ew + eb) --------
// 8 lanes per node, 32 nodes per 256-thread block, unroll x4.
// src pre-scaled by 32 in CSR payload; gather base hoisted to hb = d_h + f0.
__global__ void __launch_bounds__(256) k_agg(const float* __restrict__ ew,
                                             const float* __restrict__ eb) {
    __shared__ float w[96];
    __shared__ float b[32];
    for (int i = threadIdx.x; i < 96; i += 256) w[i] = ew[i];
    if (threadIdx.x < 32) b[threadIdx.x] = eb[threadIdx.x];
    __syncthreads();
    int tid = threadIdx.x;
    int node = blockIdx.x * 32 + (tid >> 3);
    int q = tid & 7;
    int f0 = q * 4;
    int start = __ldg(d_rowptr + node);
    int end = __ldg(d_rowptr + node + 1);
    const float* hb = d_h + f0;       // loop-invariant gather base
    float w0a = w[f0], w0b = w[f0 + 1], w0c = w[f0 + 2], w0d = w[f0 + 3];
    float w1a = w[32 + f0], w1b = w[32 + f0 + 1], w1c = w[32 + f0 + 2], w1d = w[32 + f0 + 3];
    float w2a = w[64 + f0], w2b = w[64 + f0 + 1], w2c = w[64 + f0 + 2], w2d = w[64 + f0 + 3];
    float ba = b[f0], bb = b[f0 + 1], bc = b[f0 + 2], bd = b[f0 + 3];
    float ax = 0.f, ay = 0.f, az = 0.f, aw = 0.f;
    int i = start;
    for (; i + 4 <= end; i += 4) {
        float4 p0 = __ldg(d_csr + i);
        float4 p1 = __ldg(d_csr + i + 1);
        float4 p2 = __ldg(d_csr + i + 2);
        float4 p3 = __ldg(d_csr + i + 3);
        float4 h0 = __ldg((const float4*)(hb + __float_as_int(p0.x)));
        float4 h1 = __ldg((const float4*)(hb + __float_as_int(p1.x)));
        float4 h2 = __ldg((const float4*)(hb + __float_as_int(p2.x)));
        float4 h3 = __ldg((const float4*)(hb + __float_as_int(p3.x)));
        ax += fmaxf(0.f, h0.x + ba + p0.y * w0a + p0.z * w1a + p0.w * w2a);
        ay += fmaxf(0.f, h0.y + bb + p0.y * w0b + p0.z * w1b + p0.w * w2b);
        az += fmaxf(0.f, h0.z + bc + p0.y * w0c + p0.z * w1c + p0.w * w2c);
        aw += fmaxf(0.f, h0.w + bd + p0.y * w0d + p0.z * w1d + p0.w * w2d);
        ax += fmaxf(0.f, h1.x + ba + p1.y * w0a + p1.z * w1a + p1.w * w2a);
        ay += fmaxf(0.f, h1.y + bb + p1.y * w0b + p1.z * w1b + p1.w * w2b);
        az += fmaxf(0.f, h1.z + bc + p1.y * w0c + p1.z * w1c + p1.w * w2c);
        aw += fmaxf(0.f, h1.w + bd + p1.y * w0d + p1.z * w1d + p1.w * w2d);
        ax += fmaxf(0.f, h2.x + ba + p2.y * w0a + p2.z * w1a + p2.w * w2a);
        ay += fmaxf(0.f, h2.y + bb + p2.y * w0b + p2.z * w1b + p2.w * w2b);
        az += fmaxf(0.f, h2.z + bc + p2.y * w0c + p2.z * w1c + p2.w * w2c);
        aw += fmaxf(0.f, h2.w + bd + p2.y * w0d + p2.z * w1d + p2.w * w2d);
        ax += fmaxf(0.f, h3.x + ba + p3.y * w0a + p3.z * w1a + p3.w * w2a);
        ay += fmaxf(0.f, h3.y + bb + p3.y * w0b + p3.z * w1b + p3.w * w2b);
        az += fmaxf(0.f, h3.z + bc + p3.y * w0c + p3.z * w1c + p3.w * w2c);
        aw += fmaxf(0.f, h3.w + bd + p3.y * w0d + p3.z * w1d + p3.w * w2d);
    }
    for (; i < end; i++) {
        float4 p0 = __ldg(d_csr + i);
        float4 h0 = __ldg((const float4*)(hb + __float_as_int(p0.x)));
        ax += fmaxf(0.f, h0.x + ba + p0.y * w0a + p0.z * w1a + p0.w * w2a);
        ay += fmaxf(0.f, h0.y + bb + p0.y * w0b + p0.z * w1b + p0.w * w2b);
        az += fmaxf(0.f, h0.z + bc + p0.y * w0c + p0.z * w1c + p0.w * w2c);
        aw += fmaxf(0.f, h0.w + bd + p0.y * w0d + p0.z * w1d + p0.w * w2d);
    }
    float4 hs = *(const float4*)(hb + node * 32);
    float4 o;
    o.x = hs.x + ax; o.y = hs.y + ay; o.z = hs.z + az; o.w = hs.w + aw;
    *(float4*)(d_z + node * 32 + f0) = o;
}

// -------- MLP: 128 nodes/block, smem-staged, fma2 register-blocked --------
#define ZS_OFF 0
#define HS_OFF 4224
#define W1_OFF (HS_OFF + 128 * 81)
#define W2_OFF (W1_OFF + 32 * 80)
#define B1_OFF (W2_OFF + 2400)
#define MLP_SMEM ((B1_OFF + 80) * 4)

__global__ void __launch_bounds__(256) k_mlp(int l,
        const float* __restrict__ w1, const float* __restrict__ b1,
        const float* __restrict__ w2, const float* __restrict__ b2) {
    extern __shared__ float sm[];
    float* Zs = sm + ZS_OFF;
    float* Hs = sm + HS_OFF;
    float* W1s = sm + W1_OFF;
    float* W2s = sm + W2_OFF;
    float* B1s = sm + B1_OFF;
    int tid = threadIdx.x;
    const float* w1l = w1 + l * 2400;
    const float* w2l = w2 + l * 2400;
    for (int i = tid; i < 32 * 80; i += 256) {
        int k = i / 80, j = i % 80;
        W1s[i] = (j < 75) ? w1l[k * 75 + j] : 0.f;
    }
    for (int i = tid; i < 2400; i += 256) W2s[i] = w2l[i];
    if (tid < 80) B1s[tid] = (tid < 75) ? b1[l * 75 + tid] : 0.f;

    int base = blockIdx.x * 128;
    int rows = min(128, NN - base);
    for (int i = tid; i < rows * 32; i += 256)
        Zs[(i >> 5) * 33 + (i & 31)] = d_z[base * 32 + i];
    __syncthreads();

    int lane = tid & 31;
    int wid = tid >> 5;

    // ---- phase 1 ----
    {
        int jb2 = wid * 5;
        const ull* B1u = (const ull*)B1s;
        ull acc[4][5];
#pragma unroll
        for (int jj = 0; jj < 5; jj++) {
            ull bias = B1u[jb2 + jj];
            acc[0][jj] = bias; acc[1][jj] = bias; acc[2][jj] = bias; acc[3][jj] = bias;
        }
#pragma unroll 4
        for (int k = 0; k < 32; k++) {
            const ull* wr = (const ull*)(W1s + k * 80) + jb2;
            ull w0 = wr[0], w1v = wr[1], w2v = wr[2], w3 = wr[3], w4 = wr[4];
#pragma unroll
            for (int i = 0; i < 4; i++) {
                int n = lane + 32 * i;
                float zv = (n < rows) ? Zs[n * 33 + k] : 0.f;
                ull zp = pack2(zv, zv);
                acc[i][0] = fma2(zp, w0, acc[i][0]);
                acc[i][1] = fma2(zp, w1v, acc[i][1]);
                acc[i][2] = fma2(zp, w2v, acc[i][2]);
                acc[i][3] = fma2(zp, w3, acc[i][3]);
                acc[i][4] = fma2(zp, w4, acc[i][4]);
            }
        }
        int jb = wid * 10;
#pragma unroll
        for (int i = 0; i < 4; i++) {
            int n = lane + 32 * i;
#pragma unroll
            for (int jj = 0; jj < 5; jj++) {
                Hs[n * 81 + jb + 2 * jj]     = fmaxf(0.f, lo32(acc[i][jj]));
                Hs[n * 81 + jb + 2 * jj + 1] = fmaxf(0.f, hi32(acc[i][jj]));
            }
        }
    }
    __syncthreads();

    // ---- phase 2 ----
    int f0 = wid * 4;
    ull bias0 = pack2(__ldg(b2 + l * 32 + f0), __ldg(b2 + l * 32 + f0 + 1));
    ull bias1 = pack2(__ldg(b2 + l * 32 + f0 + 2), __ldg(b2 + l * 32 + f0 + 3));
    ull acc2[4][2];
#pragma unroll
    for (int i = 0; i < 4; i++) { acc2[i][0] = bias0; acc2[i][1] = bias1; }
#pragma unroll 5
    for (int k = 0; k < 75; k++) {
        ulonglong2 wv = *(const ulonglong2*)(W2s + k * 32 + f0);
#pragma unroll
        for (int i = 0; i < 4; i++) {
            float hv = Hs[(lane + 32 * i) * 81 + k];
            ull hp = pack2(hv, hv);
            acc2[i][0] = fma2(hp, wv.x, acc2[i][0]);
            acc2[i][1] = fma2(hp, wv.y, acc2[i][1]);
        }
    }
    float s[4] = {0.f, 0.f, 0.f, 0.f};
    float q[4] = {0.f, 0.f, 0.f, 0.f};
#pragma unroll
    for (int i = 0; i < 4; i++) {
        int n = lane + 32 * i;
        if (n < rows) {
            float v0 = lo32(acc2[i][0]), v1 = hi32(acc2[i][0]);
            float v2 = lo32(acc2[i][1]), v3 = hi32(acc2[i][1]);
            s[0] += v0; q[0] += v0 * v0;
            s[1] += v1; q[1] += v1 * v1;
            s[2] += v2; q[2] += v2 * v2;
            s[3] += v3; q[3] += v3 * v3;
        }
    }
    __syncthreads();
#pragma unroll
    for (int i = 0; i < 4; i++) {
        int n = lane + 32 * i;
        Zs[n * 33 + f0]     = lo32(acc2[i][0]);
        Zs[n * 33 + f0 + 1] = hi32(acc2[i][0]);
        Zs[n * 33 + f0 + 2] = lo32(acc2[i][1]);
        Zs[n * 33 + f0 + 3] = hi32(acc2[i][1]);
    }
#pragma unroll
    for (int off = 16; off; off >>= 1) {
#pragma unroll
        for (int c = 0; c < 4; c++) {
            s[c] += __shfl_down_sync(0xffffffffu, s[c], off);
            q[c] += __shfl_down_sync(0xffffffffu, q[c], off);
        }
    }
    if (lane == 0) {
#pragma unroll
        for (int c = 0; c < 4; c++) {
            atomicAdd(&d_bnstat[l * 64 + f0 + c], s[c]);
            atomicAdd(&d_bnstat[l * 64 + 32 + f0 + c], q[c]);
        }
    }
    __syncthreads();
    for (int i = tid; i < rows * 32; i += 256)
        d_z2[base * 32 + i] = Zs[(i >> 5) * 33 + (i & 31)];
}

// -------- BN normalize + relu (scale computed in-block); mode 0: write h; mode 1: pool --------
__global__ void k_bnnorm(int l, int mode, const int* __restrict__ batch,
                         const float* __restrict__ bng, const float* __restrict__ bnb) {
    __shared__ float sc[32], sh[32];
    if (threadIdx.x < 32) {
        int f = threadIdx.x;
        float s = d_bnstat[l * 64 + f];
        float q = d_bnstat[l * 64 + 32 + f];
        float mu = s / (float)NN;
        float var = q / (float)NN - mu * mu;
        float r = rsqrtf(var + 1e-5f);
        float scv = bng[l * 32 + f] * r;
        sc[f] = scv;
        sh[f] = bnb[l * 32 + f] - mu * scv;
    }
    __syncthreads();
    int i = blockIdx.x * blockDim.x + threadIdx.x;
    if (i >= NN * 8) return;
    float4 v = ((const float4*)d_z2)[i];
    int f0 = (i & 7) * 4;
    float4 r;
    r.x = fmaxf(0.f, v.x * sc[f0 + 0] + sh[f0 + 0]);
    r.y = fmaxf(0.f, v.y * sc[f0 + 1] + sh[f0 + 1]);
    r.z = fmaxf(0.f, v.z * sc[f0 + 2] + sh[f0 + 2]);
    r.w = fmaxf(0.f, v.w * sc[f0 + 3] + sh[f0 + 3]);
    if (mode == 0) {
        ((float4*)d_h)[i] = r;
    } else {
        int n = i >> 3;
        int g = __ldg(batch + n);
        float* p = d_pool + g * 32 + f0;
        asm volatile("red.global.add.v4.f32 [%0], {%1,%2,%3,%4};"
                     :: "l"(p), "f"(r.x), "f"(r.y), "f"(r.z), "f"(r.w) : "memory");
        if ((i & 7) == 0) atomicAdd(&d_cnt[g], 1.f);
    }
}

// -------- readout head --------
__global__ void k_head(const float* __restrict__ w1, const float* __restrict__ b1,
                       const float* __restrict__ w2, const float* __restrict__ b2,
                       float* __restrict__ out) {
    __shared__ float W1[32 * 16];
    __shared__ float B1[16];
    __shared__ float W2[32];
    __shared__ float B2[2];
    for (int i = threadIdx.x; i < 512; i += blockDim.x) W1[i] = w1[i];
    if (threadIdx.x < 16) B1[threadIdx.x] = b1[threadIdx.x];
    if (threadIdx.x < 32) W2[threadIdx.x] = w2[threadIdx.x];
    if (threadIdx.x < 2) B2[threadIdx.x] = b2[threadIdx.x];
    __syncthreads();
    int g = blockIdx.x * blockDim.x + threadIdx.x;
    if (g >= NG) return;
    float inv = 1.f / fmaxf(d_cnt[g], 1.f);
    float gv[32];
#pragma unroll
    for (int k = 0; k < 32; k++) gv[k] = d_pool[g * 32 + k] * inv;
    float o0 = B2[0], o1 = B2[1];
#pragma unroll
    for (int j = 0; j < 16; j++) {
        float hj = B1[j];
#pragma unroll
        for (int k = 0; k < 32; k++) hj += gv[k] * W1[k * 16 + j];
        hj = fmaxf(hj, 0.f);
        o0 += hj * W2[j * 2 + 0];
        o1 += hj * W2[j * 2 + 1];
    }
    out[g * 2 + 0] = o0;
    out[g * 2 + 1] = o1;
}

extern "C" void kernel_launch(void* const* d_in, const int* in_sizes, int n_in,
                              void* d_out, int out_size) {
    const float* x    = (const float*)d_in[0];
    const int*   ei   = (const int*)  d_in[1];
    const float* ea   = (const float*)d_in[2];
    const int*   batch= (const int*)  d_in[3];
    const float* nw   = (const float*)d_in[4];
    const float* nb   = (const float*)d_in[5];
    const float* ew   = (const float*)d_in[6];
    const float* eb   = (const float*)d_in[7];
    const float* w1   = (const float*)d_in[8];
    const float* b1   = (const float*)d_in[9];
    const float* w2   = (const float*)d_in[10];
    const float* b2   = (const float*)d_in[11];
    const float* bng  = (const float*)d_in[12];
    const float* bnb  = (const float*)d_in[13];
    const float* l1w  = (const float*)d_in[14];
    const float* l1b  = (const float*)d_in[15];
    const float* l2w  = (const float*)d_in[16];
    const float* l2b  = (const float*)d_in[17];
    float* out = (float*)d_out;

    cudaFuncSetAttribute(k_mlp, cudaFuncAttributeMaxDynamicSharedMemorySize, MLP_SMEM);

    k_zero<<<256, 256>>>();
    k_hist<<<(NE + 255) / 256, 256>>>(ei);
    k_scan<<<SCAN_BLK, 1024>>>();
    k_scatter<<<(NE + 255) / 256, 256>>>(ei, ea);
    k_embed<<<(NN + 255) / 256, 256>>>(x, nw, nb);
    for (int l = 0; l < 2; l++) {
        k_agg<<<NN / 32, 256>>>(ew, eb);
        k_mlp<<<(NN + 127) / 128, 256, MLP_SMEM>>>(l, w1, b1, w2, b2);
        k_bnnorm<<<(NN * 8 + 255) / 256, 256>>>(l, l == 0 ? 0 : 1, batch, bng, bnb);
    }
    k_head<<<(NG + 255) / 256, 256>>>(l1w, l1b, l2w, l2b, out);
}